// round 1
// baseline (speedup 1.0000x reference)
#include <cuda_runtime.h>
#include <cstdint>

// Problem constants (FixedRadiusNNGraph: B=2, N=8192, F=64, radius=0.3)
#define BB 2
#define NN 8192
#define FF 64
#define R2 0.09f

// Scratch: packed points (x, y, z, ||p||^2). 16384 * 16B = 256 KB.
__device__ float4 g_pts4[BB * NN];

__global__ void prep_kernel(const float* __restrict__ pts) {
    int i = blockIdx.x * blockDim.x + threadIdx.x;
    if (i < BB * NN) {
        float x = pts[3 * i + 0];
        float y = pts[3 * i + 1];
        float z = pts[3 * i + 2];
        g_pts4[i] = make_float4(x, y, z, x * x + y * y + z * z);
    }
}

// Each thread: 4 contiguous j (one float4 store per output per row),
// each block: 8 i-rows x 1024 j. Pure write-bound; pj reads amortized 8x.
__global__ __launch_bounds__(256) void frnn_kernel(
    float* __restrict__ adj_out,   // may be null
    float* __restrict__ dist_out)  // may be null
{
    const int b  = blockIdx.z;
    const int i0 = blockIdx.y * 8;
    const int j0 = (blockIdx.x * 256 + threadIdx.x) * 4;

    const float4* __restrict__ p = g_pts4 + b * NN;

    const float4 q0 = p[j0 + 0];
    const float4 q1 = p[j0 + 1];
    const float4 q2 = p[j0 + 2];
    const float4 q3 = p[j0 + 3];

    const size_t base = (size_t)b * NN * NN + (size_t)i0 * NN + j0;

#pragma unroll
    for (int ii = 0; ii < 8; ii++) {
        const float4 pi = p[i0 + ii];

        float4 d;
        d.x = (pi.w + q0.w) - 2.0f * (pi.x * q0.x + pi.y * q0.y + pi.z * q0.z);
        d.y = (pi.w + q1.w) - 2.0f * (pi.x * q1.x + pi.y * q1.y + pi.z * q1.z);
        d.z = (pi.w + q2.w) - 2.0f * (pi.x * q2.x + pi.y * q2.y + pi.z * q2.z);
        d.w = (pi.w + q3.w) - 2.0f * (pi.x * q3.x + pi.y * q3.y + pi.z * q3.z);

        float4 a;
        a.x = (d.x <= R2) ? 1.0f : 0.0f;
        a.y = (d.y <= R2) ? 1.0f : 0.0f;
        a.z = (d.z <= R2) ? 1.0f : 0.0f;
        a.w = (d.w <= R2) ? 1.0f : 0.0f;

        const size_t off = base + (size_t)ii * NN;
        if (dist_out) *reinterpret_cast<float4*>(dist_out + off) = d;
        if (adj_out)  *reinterpret_cast<float4*>(adj_out + off) = a;
    }
}

extern "C" void kernel_launch(void* const* d_in, const int* in_sizes, int n_in,
                              void* d_out, int out_size)
{
    const float* batch_points = (const float*)d_in[0];
    const float* batch_feats  = (const float*)d_in[1];
    // d_in[2] = batch_len (offsets [0, N, 2N]) — shapes are static, unused.

    float* out = (float*)d_out;

    const long long bnn   = (long long)BB * NN * NN;          // 134,217,728
    const long long npts  = (long long)BB * NN * 3;           // 49,152
    const long long nfeat = (long long)BB * NN * FF;          // 1,048,576
    const long long full  = 2 * bnn + npts + nfeat;

    // Stage packed points + squared norms.
    prep_kernel<<<(BB * NN + 255) / 256, 256>>>(batch_points);

    // Resolve output layout from out_size (hedge against flattening variants).
    float* adj_ptr  = nullptr;
    float* dist_ptr = nullptr;
    bool copy_tail  = false;

    const long long osz = (long long)out_size;
    if (osz >= full) {
        adj_ptr  = out;
        dist_ptr = out + bnn;
        copy_tail = true;
    } else if (osz >= 2 * bnn) {
        adj_ptr  = out;
        dist_ptr = out + bnn;
    } else {
        adj_ptr = out;  // adj-only fallback
    }

    dim3 grid(NN / (256 * 4), NN / 8, BB);   // (8, 1024, 2)
    frnn_kernel<<<grid, 256>>>(adj_ptr, dist_ptr);

    if (copy_tail) {
        // pts and feats are bit-identical reshapes of the inputs.
        cudaMemcpyAsync(out + 2 * bnn, batch_points, npts * sizeof(float),
                        cudaMemcpyDeviceToDevice, 0);
        cudaMemcpyAsync(out + 2 * bnn + npts, batch_feats, nfeat * sizeof(float),
                        cudaMemcpyDeviceToDevice, 0);
    }
}

// round 2
// speedup vs baseline: 1.0444x; 1.0444x over previous
#include <cuda_runtime.h>
#include <cstdint>

// FixedRadiusNNGraph: B=2, N=8192, F=64, radius=0.3
#define BB 2
#define NN 8192
#define FF 64
#define R2 0.09f

#define TILE_BLOCKS 16384           // (NN/1024 j-tiles=8) * (NN/8 rowgroups=1024) * B=2
#define COPY_BLOCKS 112
#define NPTS   (BB * NN * 3)        // 49,152 floats
#define NFEAT  (BB * NN * FF)       // 1,048,576 floats
#define TAIL_V4 ((NPTS + NFEAT) / 4) // 274,432 float4
#define PTS_V4 (NPTS / 4)            // 12,288 float4

__device__ __forceinline__ void stream_st(float* p, float4 v) {
    __stcs(reinterpret_cast<float4*>(p), v);
}

// One fused kernel: 16384 tile blocks write adj+dists (write-bound),
// 112 trailing blocks copy the pts/feats pass-through tail.
__global__ __launch_bounds__(256) void frnn_fused_kernel(
    const float* __restrict__ pts,
    const float* __restrict__ feats,
    float* __restrict__ out)
{
    const long long bnn = (long long)BB * NN * NN;
    const int bx = blockIdx.x;

    if (bx >= TILE_BLOCKS) {
        // ---- tail copy: [pts | feats] -> out + 2*bnn, as float4 ----
        const int cb = bx - TILE_BLOCKS;
        float* dst = out + 2 * bnn;
        const float4* src_p = reinterpret_cast<const float4*>(pts);
        const float4* src_f = reinterpret_cast<const float4*>(feats);
        for (int t = cb * 256 + threadIdx.x; t < TAIL_V4; t += COPY_BLOCKS * 256) {
            float4 v = (t < PTS_V4) ? __ldg(src_p + t) : __ldg(src_f + (t - PTS_V4));
            stream_st(dst + 4 * (size_t)t, v);
        }
        return;
    }

    // ---- tile work: block covers 8 i-rows x 1024 j ----
    const int jt = bx & 7;
    const int rg = (bx >> 3) & 1023;
    const int b  = bx >> 13;
    const int i0 = rg * 8;
    const int j0 = (jt * 256 + threadIdx.x) * 4;

    const float* p = pts + (size_t)b * NN * 3;

    // 4 contiguous j-points: 12 floats = 3 aligned float4 loads (j0 % 4 == 0).
    const float4* jv = reinterpret_cast<const float4*>(p + (size_t)j0 * 3);
    const float4 v0 = __ldg(jv + 0), v1 = __ldg(jv + 1), v2 = __ldg(jv + 2);
    const float qx0 = v0.x, qy0 = v0.y, qz0 = v0.z;
    const float qx1 = v0.w, qy1 = v1.x, qz1 = v1.y;
    const float qx2 = v1.z, qy2 = v1.w, qz2 = v2.x;
    const float qx3 = v2.y, qy3 = v2.z, qz3 = v2.w;
    const float qn0 = qx0*qx0 + qy0*qy0 + qz0*qz0;
    const float qn1 = qx1*qx1 + qy1*qy1 + qz1*qz1;
    const float qn2 = qx2*qx2 + qy2*qy2 + qz2*qz2;
    const float qn3 = qx3*qx3 + qy3*qy3 + qz3*qz3;

    // 8 i-points: 24 floats = 6 aligned float4 loads (i0 % 8 == 0).
    const float4* iv = reinterpret_cast<const float4*>(p + (size_t)i0 * 3);
    const float4 w0 = __ldg(iv + 0), w1 = __ldg(iv + 1), w2 = __ldg(iv + 2);
    const float4 w3 = __ldg(iv + 3), w4 = __ldg(iv + 4), w5 = __ldg(iv + 5);
    const float pix[8] = {w0.x, w0.w, w1.z, w2.y, w3.x, w3.w, w4.z, w5.y};
    const float piy[8] = {w0.y, w1.x, w1.w, w2.z, w3.y, w4.x, w4.w, w5.z};
    const float piz[8] = {w0.z, w1.y, w2.x, w2.w, w3.z, w4.y, w5.x, w5.w};

    float* adj_out  = out;
    float* dist_out = out + bnn;
    const size_t base = (size_t)b * NN * NN + (size_t)i0 * NN + j0;

#pragma unroll
    for (int ii = 0; ii < 8; ii++) {
        const float x = pix[ii], y = piy[ii], z = piz[ii];
        const float pn = x*x + y*y + z*z;

        float4 d;
        d.x = (pn + qn0) - 2.0f * (x*qx0 + y*qy0 + z*qz0);
        d.y = (pn + qn1) - 2.0f * (x*qx1 + y*qy1 + z*qz1);
        d.z = (pn + qn2) - 2.0f * (x*qx2 + y*qy2 + z*qz2);
        d.w = (pn + qn3) - 2.0f * (x*qx3 + y*qy3 + z*qz3);

        float4 a;
        a.x = (d.x <= R2) ? 1.0f : 0.0f;
        a.y = (d.y <= R2) ? 1.0f : 0.0f;
        a.z = (d.z <= R2) ? 1.0f : 0.0f;
        a.w = (d.w <= R2) ? 1.0f : 0.0f;

        const size_t off = base + (size_t)ii * NN;
        stream_st(dist_out + off, d);
        stream_st(adj_out + off, a);
    }
}

extern "C" void kernel_launch(void* const* d_in, const int* in_sizes, int n_in,
                              void* d_out, int out_size)
{
    const float* batch_points = (const float*)d_in[0];
    const float* batch_feats  = (const float*)d_in[1];
    // d_in[2] = batch_len: static uniform offsets, unused.

    frnn_fused_kernel<<<TILE_BLOCKS + COPY_BLOCKS, 256>>>(
        batch_points, batch_feats, (float*)d_out);
}